// round 1
// baseline (speedup 1.0000x reference)
#include <cuda_runtime.h>
#include <cstdint>

// ---------------- static scratch (no allocs allowed) ----------------
__device__ float g_xg[32768 * 3072];      // input-projection buffer (max 3H=3072)
__device__ float g_actA[32768 * 1024];    // layer activations ping
__device__ float g_actB[32768 * 1024];    // raw GRU outputs (pre-LN)
__device__ float g_h[64 * 1024];          // current hidden state broadcast
__device__ unsigned g_arrive;
__device__ unsigned g_release;

// ---------------- helpers ----------------
__device__ __forceinline__ unsigned f2tf(float x) {
    unsigned r; asm("cvt.rna.tf32.f32 %0, %1;" : "=r"(r) : "f"(x)); return r;
}

__device__ __forceinline__ void mma8(float* c, const unsigned* a, const unsigned* b) {
    asm volatile("mma.sync.aligned.m16n8k8.row.col.f32.tf32.tf32.f32 "
                 "{%0,%1,%2,%3}, {%4,%5,%6,%7}, {%8,%9}, {%0,%1,%2,%3};"
                 : "+f"(c[0]), "+f"(c[1]), "+f"(c[2]), "+f"(c[3])
                 : "r"(a[0]), "r"(a[1]), "r"(a[2]), "r"(a[3]),
                   "r"(b[0]), "r"(b[1]));
}

// ---------------- input-projection GEMM: C[m,n] = sum_k A[m,k]*B[n,k] ----------------
// A: [32768, K] row-major, B: [N, K] row-major, C: [32768, N]
// CTA tile 128x64, 8 warps (4M x 2N), warp tile 32x32 (2 m-frags x 4 n-frags)
template<int K>
__global__ void __launch_bounds__(256) gemm_xg(const float* __restrict__ A,
                                               const float* __restrict__ B,
                                               float* __restrict__ C, int N) {
    __shared__ unsigned As[128 * 33];
    __shared__ unsigned Bs[64 * 33];
    const int m0 = blockIdx.y * 128;
    const int n0 = blockIdx.x * 64;
    const int tid = threadIdx.x;
    const int lane = tid & 31, wid = tid >> 5;
    const int wm = (wid & 3) * 32, wn = (wid >> 2) * 32;

    float acc[2][4][4];
#pragma unroll
    for (int i = 0; i < 2; i++)
#pragma unroll
        for (int j = 0; j < 4; j++)
#pragma unroll
            for (int k = 0; k < 4; k++) acc[i][j][k] = 0.f;

    const int lr = tid >> 3;        // 0..31
    const int lc = (tid & 7) * 4;   // 0..28

    for (int kc = 0; kc < K; kc += 32) {
#pragma unroll
        for (int i = 0; i < 4; i++) {
            int r = lr + i * 32;
            float4 v = *reinterpret_cast<const float4*>(&A[(size_t)(m0 + r) * K + kc + lc]);
            As[r * 33 + lc + 0] = f2tf(v.x); As[r * 33 + lc + 1] = f2tf(v.y);
            As[r * 33 + lc + 2] = f2tf(v.z); As[r * 33 + lc + 3] = f2tf(v.w);
        }
#pragma unroll
        for (int i = 0; i < 2; i++) {
            int r = lr + i * 32;
            float4 v = *reinterpret_cast<const float4*>(&B[(size_t)(n0 + r) * K + kc + lc]);
            Bs[r * 33 + lc + 0] = f2tf(v.x); Bs[r * 33 + lc + 1] = f2tf(v.y);
            Bs[r * 33 + lc + 2] = f2tf(v.z); Bs[r * 33 + lc + 3] = f2tf(v.w);
        }
        __syncthreads();
#pragma unroll
        for (int k8 = 0; k8 < 4; k8++) {
            const int kb = k8 * 8;
            unsigned a[2][4], b[4][2];
#pragma unroll
            for (int mf = 0; mf < 2; mf++) {
                int rb = wm + mf * 16 + (lane >> 2);
                a[mf][0] = As[rb * 33 + kb + (lane & 3)];
                a[mf][1] = As[(rb + 8) * 33 + kb + (lane & 3)];
                a[mf][2] = As[rb * 33 + kb + (lane & 3) + 4];
                a[mf][3] = As[(rb + 8) * 33 + kb + (lane & 3) + 4];
            }
#pragma unroll
            for (int nf = 0; nf < 4; nf++) {
                int cb = wn + nf * 8 + (lane >> 2);
                b[nf][0] = Bs[cb * 33 + kb + (lane & 3)];
                b[nf][1] = Bs[cb * 33 + kb + (lane & 3) + 4];
            }
#pragma unroll
            for (int mf = 0; mf < 2; mf++)
#pragma unroll
                for (int nf = 0; nf < 4; nf++)
                    mma8(acc[mf][nf], a[mf], b[nf]);
        }
        __syncthreads();
    }
#pragma unroll
    for (int mf = 0; mf < 2; mf++)
#pragma unroll
        for (int nf = 0; nf < 4; nf++) {
            int row = m0 + wm + mf * 16 + (lane >> 2);
            int col = n0 + wn + nf * 8 + 2 * (lane & 3);
            C[(size_t)row * N + col]     = acc[mf][nf][0];
            C[(size_t)row * N + col + 1] = acc[mf][nf][1];
            C[(size_t)(row + 8) * N + col]     = acc[mf][nf][2];
            C[(size_t)(row + 8) * N + col + 1] = acc[mf][nf][3];
        }
}

// ---------------- persistent GRU recurrence ----------------
// grid = H/16 CTAs (all co-resident), block = 128 threads (4 warps: 2M x 2N, warp = m32 x n24)
// Each CTA owns 16 h-columns; its 48xH Whh slice lives in SMEM (tf32) for all 512 steps.
template<int H>
__global__ void __launch_bounds__(128) gru_rec(const float* __restrict__ Whh,
                                               const float* __restrict__ xg,
                                               float* __restrict__ y) {
    constexpr int NT = 16;
    constexpr int WSP = H + 1;   // padded stride (odd) -> conflict-free n-major reads
    extern __shared__ unsigned char smem_raw[];
    unsigned* Ws = reinterpret_cast<unsigned*>(smem_raw);   // [48][WSP] tf32 Whh slice
    unsigned* As = Ws + 48 * WSP;                           // [64][33]  tf32 h chunk
    float* hgS = reinterpret_cast<float*>(As + 64 * 33);    // [64][49]  hg slice
    float* hl  = hgS + 64 * 49;                             // [64][16]  local h (own cols)

    const int tid = threadIdx.x;
    const int lane = tid & 31, wid = tid >> 5;
    const int wm = (wid & 1) * 32;
    const int wn = (wid >> 1) * 24;
    const int c0 = blockIdx.x * NT;
    const unsigned nCTA = gridDim.x;

    // one-time: Whh slice -> SMEM (tf32), zero local h
    {
        const int nf4 = H / 4;
        for (int idx = tid; idx < 48 * nf4; idx += 128) {
            int rr = idx / nf4;
            int c4 = (idx % nf4) * 4;
            int gate = rr >> 4;
            int j = rr & 15;
            int grow = gate * H + c0 + j;
            float4 v = *reinterpret_cast<const float4*>(&Whh[(size_t)grow * H + c4]);
            Ws[rr * WSP + c4 + 0] = f2tf(v.x); Ws[rr * WSP + c4 + 1] = f2tf(v.y);
            Ws[rr * WSP + c4 + 2] = f2tf(v.z); Ws[rr * WSP + c4 + 3] = f2tf(v.w);
        }
        for (int idx = tid; idx < 64 * 16; idx += 128) hl[idx] = 0.f;
    }
    __syncthreads();

    const int lr = tid >> 3;        // 0..15
    const int lc = (tid & 7) * 4;   // 0..28

    for (int t = 0; t < 512; t++) {
        float acc[2][3][4];
#pragma unroll
        for (int i = 0; i < 2; i++)
#pragma unroll
            for (int j = 0; j < 3; j++)
#pragma unroll
                for (int k = 0; k < 4; k++) acc[i][j][k] = 0.f;

        if (t > 0) {
            for (int kc = 0; kc < H; kc += 32) {
#pragma unroll
                for (int i = 0; i < 4; i++) {
                    int r = lr + i * 16;
                    float4 v = __ldcg(reinterpret_cast<const float4*>(&g_h[r * H + kc + lc]));
                    As[r * 33 + lc + 0] = f2tf(v.x); As[r * 33 + lc + 1] = f2tf(v.y);
                    As[r * 33 + lc + 2] = f2tf(v.z); As[r * 33 + lc + 3] = f2tf(v.w);
                }
                __syncthreads();
#pragma unroll
                for (int k8 = 0; k8 < 4; k8++) {
                    const int kb = k8 * 8;
                    unsigned a[2][4], b[3][2];
#pragma unroll
                    for (int mf = 0; mf < 2; mf++) {
                        int rb = wm + mf * 16 + (lane >> 2);
                        a[mf][0] = As[rb * 33 + kb + (lane & 3)];
                        a[mf][1] = As[(rb + 8) * 33 + kb + (lane & 3)];
                        a[mf][2] = As[rb * 33 + kb + (lane & 3) + 4];
                        a[mf][3] = As[(rb + 8) * 33 + kb + (lane & 3) + 4];
                    }
#pragma unroll
                    for (int nf = 0; nf < 3; nf++) {
                        int cb = wn + nf * 8 + (lane >> 2);
                        b[nf][0] = Ws[cb * WSP + kc + kb + (lane & 3)];
                        b[nf][1] = Ws[cb * WSP + kc + kb + (lane & 3) + 4];
                    }
#pragma unroll
                    for (int mf = 0; mf < 2; mf++)
#pragma unroll
                        for (int nf = 0; nf < 3; nf++)
                            mma8(acc[mf][nf], a[mf], b[nf]);
                }
                __syncthreads();
            }
        }
        // accumulators -> hg slice in SMEM
#pragma unroll
        for (int mf = 0; mf < 2; mf++)
#pragma unroll
            for (int nf = 0; nf < 3; nf++) {
                int row = wm + mf * 16 + (lane >> 2);
                int col = wn + nf * 8 + 2 * (lane & 3);
                hgS[row * 49 + col]           = acc[mf][nf][0];
                hgS[row * 49 + col + 1]       = acc[mf][nf][1];
                hgS[(row + 8) * 49 + col]     = acc[mf][nf][2];
                hgS[(row + 8) * 49 + col + 1] = acc[mf][nf][3];
            }
        __syncthreads();
        // gate epilogue: 64 batches x 16 cols = 1024 items / 128 threads
        {
            const int j = tid & 15;
#pragma unroll
            for (int it = 0; it < 8; it++) {
                int bb = (tid >> 4) + it * 8;
                size_t m = (size_t)bb * 512 + t;
                const float* xrow = xg + m * (size_t)(3 * H);
                float xr = xrow[c0 + j];
                float xz = xrow[H + c0 + j];
                float xn = xrow[2 * H + c0 + j];
                float hr = hgS[bb * 49 + j];
                float hz = hgS[bb * 49 + 16 + j];
                float hn = hgS[bb * 49 + 32 + j];
                float r = 1.f / (1.f + __expf(-(xr + hr)));
                float z = 1.f / (1.f + __expf(-(xz + hz)));
                float n = tanhf(xn + r * hn);
                float hnew = (1.f - z) * n + z * hl[bb * 16 + j];
                hl[bb * 16 + j] = hnew;
                __stcg(&g_h[bb * H + c0 + j], hnew);
                y[m * (size_t)H + c0 + j] = hnew;
            }
        }
        if (t < 511) {
            // grid barrier: release h writes, acquire others'
            __syncthreads();
            if (tid == 0) {
                unsigned prev;
                asm volatile("atom.release.gpu.add.u32 %0, [%1], 1;"
                             : "=r"(prev) : "l"(&g_arrive) : "memory");
                unsigned tgt = nCTA * (unsigned)(t + 1);
                if (prev + 1u == tgt) {
                    asm volatile("st.release.gpu.u32 [%0], %1;"
                                 :: "l"(&g_release), "r"((unsigned)(t + 1)) : "memory");
                } else {
                    unsigned v;
                    do {
                        asm volatile("ld.acquire.gpu.u32 %0, [%1];"
                                     : "=r"(v) : "l"(&g_release) : "memory");
                    } while (v < (unsigned)(t + 1));
                }
            }
            __syncthreads();
        }
    }
}

// ---------------- LayerNorm (eps=0) ----------------
template<int H>
__global__ void __launch_bounds__(128) ln_k(const float* __restrict__ yin,
                                            const float* __restrict__ gw,
                                            const float* __restrict__ bw,
                                            float* __restrict__ outp) {
    constexpr int PER = H / 128;
    __shared__ float red[8];
    const int row = blockIdx.x, tid = threadIdx.x;
    const float* p = yin + (size_t)row * H;
    float v[PER];
    float s = 0.f;
#pragma unroll
    for (int i = 0; i < PER; i++) { v[i] = p[tid + i * 128]; s += v[i]; }
#pragma unroll
    for (int o = 16; o > 0; o >>= 1) s += __shfl_xor_sync(0xffffffffu, s, o);
    if ((tid & 31) == 0) red[tid >> 5] = s;
    __syncthreads();
    float mean = (red[0] + red[1] + red[2] + red[3]) * (1.f / H);
    float s2 = 0.f;
#pragma unroll
    for (int i = 0; i < PER; i++) { float d = v[i] - mean; s2 += d * d; }
#pragma unroll
    for (int o = 16; o > 0; o >>= 1) s2 += __shfl_xor_sync(0xffffffffu, s2, o);
    if ((tid & 31) == 0) red[4 + (tid >> 5)] = s2;
    __syncthreads();
    float var = (red[4] + red[5] + red[6] + red[7]) * (1.f / H);
    float inv = rsqrtf(var);
#pragma unroll
    for (int i = 0; i < PER; i++) {
        int c = tid + i * 128;
        outp[(size_t)row * H + c] = (v[i] - mean) * inv * gw[c] + bw[c];
    }
}

__global__ void reset_bar() { g_arrive = 0u; g_release = 0u; }

// ---------------- driver ----------------
static inline size_t rec_smem(int H) {
    return sizeof(unsigned) * (48 * (H + 1) + 64 * 33) + sizeof(float) * (64 * 49 + 64 * 16);
}

extern "C" void kernel_launch(void* const* d_in, const int* in_sizes, int n_in,
                              void* d_out, int out_size) {
    (void)in_sizes; (void)n_in; (void)out_size;
    const float* x = (const float*)d_in[0];
    const float* Wih[6]; const float* Whh[6]; const float* gw[6]; const float* bw[6];
    for (int l = 0; l < 6; l++) {
        Wih[l] = (const float*)d_in[1 + 4 * l];
        Whh[l] = (const float*)d_in[2 + 4 * l];
        gw[l]  = (const float*)d_in[3 + 4 * l];
        bw[l]  = (const float*)d_in[4 + 4 * l];
    }
    float *xg, *actA, *actB;
    cudaGetSymbolAddress((void**)&xg, g_xg);
    cudaGetSymbolAddress((void**)&actA, g_actA);
    cudaGetSymbolAddress((void**)&actB, g_actB);

    static const int DIN[6] = {128, 256, 512, 1024, 512, 256};
    static const int HH[6]  = {256, 512, 1024, 512, 256, 128};

    const float* in = x;
    for (int l = 0; l < 6; l++) {
        const int K = DIN[l], H = HH[l], N = 3 * H;
        dim3 grid(N / 64, 256);
        switch (K) {
            case 128:  gemm_xg<128><<<grid, 256>>>(in, Wih[l], xg, N); break;
            case 256:  gemm_xg<256><<<grid, 256>>>(in, Wih[l], xg, N); break;
            case 512:  gemm_xg<512><<<grid, 256>>>(in, Wih[l], xg, N); break;
            case 1024: gemm_xg<1024><<<grid, 256>>>(in, Wih[l], xg, N); break;
        }
        reset_bar<<<1, 1>>>();
        const size_t sm = rec_smem(H);
        switch (H) {
            case 128:
                cudaFuncSetAttribute(gru_rec<128>, cudaFuncAttributeMaxDynamicSharedMemorySize, (int)sm);
                gru_rec<128><<<128 / 16, 128, sm>>>(Whh[l], xg, actB); break;
            case 256:
                cudaFuncSetAttribute(gru_rec<256>, cudaFuncAttributeMaxDynamicSharedMemorySize, (int)sm);
                gru_rec<256><<<256 / 16, 128, sm>>>(Whh[l], xg, actB); break;
            case 512:
                cudaFuncSetAttribute(gru_rec<512>, cudaFuncAttributeMaxDynamicSharedMemorySize, (int)sm);
                gru_rec<512><<<512 / 16, 128, sm>>>(Whh[l], xg, actB); break;
            case 1024:
                cudaFuncSetAttribute(gru_rec<1024>, cudaFuncAttributeMaxDynamicSharedMemorySize, (int)sm);
                gru_rec<1024><<<1024 / 16, 128, sm>>>(Whh[l], xg, actB); break;
        }
        float* lnout = (l == 5) ? (float*)d_out : actA;
        switch (H) {
            case 128:  ln_k<128><<<32768, 128>>>(actB, gw[l], bw[l], lnout); break;
            case 256:  ln_k<256><<<32768, 128>>>(actB, gw[l], bw[l], lnout); break;
            case 512:  ln_k<512><<<32768, 128>>>(actB, gw[l], bw[l], lnout); break;
            case 1024: ln_k<1024><<<32768, 128>>>(actB, gw[l], bw[l], lnout); break;
        }
        in = actA;
    }
}

// round 2
// speedup vs baseline: 1.0018x; 1.0018x over previous
#include <cuda_runtime.h>
#include <cstdint>

// ---------------- static scratch (no allocs allowed) ----------------
__device__ float g_xg[32768 * 3072];      // input-projection buffer (max 3H=3072)
__device__ float g_actA[32768 * 1024];    // layer activations ping
__device__ float g_actB[32768 * 1024];    // raw GRU outputs (pre-LN)
__device__ float g_h[64 * 1024];          // current hidden state broadcast
__device__ unsigned g_arrive;
__device__ unsigned g_release;

// ---------------- helpers ----------------
__device__ __forceinline__ unsigned f2tf(float x) {
    unsigned r; asm("cvt.rna.tf32.f32 %0, %1;" : "=r"(r) : "f"(x)); return r;
}

__device__ __forceinline__ void mma8(float* c, const unsigned* a, const unsigned* b) {
    asm volatile("mma.sync.aligned.m16n8k8.row.col.f32.tf32.tf32.f32 "
                 "{%0,%1,%2,%3}, {%4,%5,%6,%7}, {%8,%9}, {%0,%1,%2,%3};"
                 : "+f"(c[0]), "+f"(c[1]), "+f"(c[2]), "+f"(c[3])
                 : "r"(a[0]), "r"(a[1]), "r"(a[2]), "r"(a[3]),
                   "r"(b[0]), "r"(b[1]));
}

// ---------------- input-projection GEMM: C[m,n] = sum_k A[m,k]*B[n,k] ----------------
// A: [32768, K] row-major, B: [N, K] row-major, C: [32768, N]
// CTA tile 128x64, 8 warps (4M x 2N), warp tile 32x32 (2 m-frags x 4 n-frags)
template<int K>
__global__ void __launch_bounds__(256) gemm_xg(const float* __restrict__ A,
                                               const float* __restrict__ B,
                                               float* __restrict__ C, int N) {
    __shared__ unsigned As[128 * 33];
    __shared__ unsigned Bs[64 * 33];
    const int m0 = blockIdx.y * 128;
    const int n0 = blockIdx.x * 64;
    const int tid = threadIdx.x;
    const int lane = tid & 31, wid = tid >> 5;
    const int wm = (wid & 3) * 32, wn = (wid >> 2) * 32;

    float acc[2][4][4];
#pragma unroll
    for (int i = 0; i < 2; i++)
#pragma unroll
        for (int j = 0; j < 4; j++)
#pragma unroll
            for (int k = 0; k < 4; k++) acc[i][j][k] = 0.f;

    const int lr = tid >> 3;        // 0..31
    const int lc = (tid & 7) * 4;   // 0..28

    for (int kc = 0; kc < K; kc += 32) {
#pragma unroll
        for (int i = 0; i < 4; i++) {
            int r = lr + i * 32;
            float4 v = *reinterpret_cast<const float4*>(&A[(size_t)(m0 + r) * K + kc + lc]);
            As[r * 33 + lc + 0] = f2tf(v.x); As[r * 33 + lc + 1] = f2tf(v.y);
            As[r * 33 + lc + 2] = f2tf(v.z); As[r * 33 + lc + 3] = f2tf(v.w);
        }
#pragma unroll
        for (int i = 0; i < 2; i++) {
            int r = lr + i * 32;
            float4 v = *reinterpret_cast<const float4*>(&B[(size_t)(n0 + r) * K + kc + lc]);
            Bs[r * 33 + lc + 0] = f2tf(v.x); Bs[r * 33 + lc + 1] = f2tf(v.y);
            Bs[r * 33 + lc + 2] = f2tf(v.z); Bs[r * 33 + lc + 3] = f2tf(v.w);
        }
        __syncthreads();
#pragma unroll
        for (int k8 = 0; k8 < 4; k8++) {
            const int kb = k8 * 8;
            unsigned a[2][4], b[4][2];
#pragma unroll
            for (int mf = 0; mf < 2; mf++) {
                int rb = wm + mf * 16 + (lane >> 2);
                a[mf][0] = As[rb * 33 + kb + (lane & 3)];
                a[mf][1] = As[(rb + 8) * 33 + kb + (lane & 3)];
                a[mf][2] = As[rb * 33 + kb + (lane & 3) + 4];
                a[mf][3] = As[(rb + 8) * 33 + kb + (lane & 3) + 4];
            }
#pragma unroll
            for (int nf = 0; nf < 4; nf++) {
                int cb = wn + nf * 8 + (lane >> 2);
                b[nf][0] = Bs[cb * 33 + kb + (lane & 3)];
                b[nf][1] = Bs[cb * 33 + kb + (lane & 3) + 4];
            }
#pragma unroll
            for (int mf = 0; mf < 2; mf++)
#pragma unroll
                for (int nf = 0; nf < 4; nf++)
                    mma8(acc[mf][nf], a[mf], b[nf]);
        }
        __syncthreads();
    }
#pragma unroll
    for (int mf = 0; mf < 2; mf++)
#pragma unroll
        for (int nf = 0; nf < 4; nf++) {
            int row = m0 + wm + mf * 16 + (lane >> 2);
            int col = n0 + wn + nf * 8 + 2 * (lane & 3);
            C[(size_t)row * N + col]     = acc[mf][nf][0];
            C[(size_t)row * N + col + 1] = acc[mf][nf][1];
            C[(size_t)(row + 8) * N + col]     = acc[mf][nf][2];
            C[(size_t)(row + 8) * N + col + 1] = acc[mf][nf][3];
        }
}

// ---------------- persistent GRU recurrence ----------------
// grid = H/16 CTAs (all co-resident), block = 128 threads (4 warps: 2M x 2N, warp = m32 x n24)
// Each CTA owns 16 h-columns; its 48xH Whh slice lives in SMEM (tf32) for all 512 steps.
template<int H>
__global__ void __launch_bounds__(128) gru_rec(const float* __restrict__ Whh,
                                               const float* __restrict__ xg,
                                               float* __restrict__ y) {
    constexpr int NT = 16;
    constexpr int WSP = H + 1;   // padded stride (odd) -> conflict-free n-major reads
    extern __shared__ unsigned char smem_raw[];
    unsigned* Ws = reinterpret_cast<unsigned*>(smem_raw);   // [48][WSP] tf32 Whh slice
    unsigned* As = Ws + 48 * WSP;                           // [64][33]  tf32 h chunk
    float* hgS = reinterpret_cast<float*>(As + 64 * 33);    // [64][49]  hg slice
    float* hl  = hgS + 64 * 49;                             // [64][16]  local h (own cols)

    const int tid = threadIdx.x;
    const int lane = tid & 31, wid = tid >> 5;
    const int wm = (wid & 1) * 32;
    const int wn = (wid >> 1) * 24;
    const int c0 = blockIdx.x * NT;
    const unsigned nCTA = gridDim.x;

    // one-time: Whh slice -> SMEM (tf32), zero local h
    {
        const int nf4 = H / 4;
        for (int idx = tid; idx < 48 * nf4; idx += 128) {
            int rr = idx / nf4;
            int c4 = (idx % nf4) * 4;
            int gate = rr >> 4;
            int j = rr & 15;
            int grow = gate * H + c0 + j;
            float4 v = *reinterpret_cast<const float4*>(&Whh[(size_t)grow * H + c4]);
            Ws[rr * WSP + c4 + 0] = f2tf(v.x); Ws[rr * WSP + c4 + 1] = f2tf(v.y);
            Ws[rr * WSP + c4 + 2] = f2tf(v.z); Ws[rr * WSP + c4 + 3] = f2tf(v.w);
        }
        for (int idx = tid; idx < 64 * 16; idx += 128) hl[idx] = 0.f;
    }
    __syncthreads();

    const int lr = tid >> 3;        // 0..15
    const int lc = (tid & 7) * 4;   // 0..28

    for (int t = 0; t < 512; t++) {
        float acc[2][3][4];
#pragma unroll
        for (int i = 0; i < 2; i++)
#pragma unroll
            for (int j = 0; j < 3; j++)
#pragma unroll
                for (int k = 0; k < 4; k++) acc[i][j][k] = 0.f;

        if (t > 0) {
            for (int kc = 0; kc < H; kc += 32) {
#pragma unroll
                for (int i = 0; i < 4; i++) {
                    int r = lr + i * 16;
                    float4 v = __ldcg(reinterpret_cast<const float4*>(&g_h[r * H + kc + lc]));
                    As[r * 33 + lc + 0] = f2tf(v.x); As[r * 33 + lc + 1] = f2tf(v.y);
                    As[r * 33 + lc + 2] = f2tf(v.z); As[r * 33 + lc + 3] = f2tf(v.w);
                }
                __syncthreads();
#pragma unroll
                for (int k8 = 0; k8 < 4; k8++) {
                    const int kb = k8 * 8;
                    unsigned a[2][4], b[3][2];
#pragma unroll
                    for (int mf = 0; mf < 2; mf++) {
                        int rb = wm + mf * 16 + (lane >> 2);
                        a[mf][0] = As[rb * 33 + kb + (lane & 3)];
                        a[mf][1] = As[(rb + 8) * 33 + kb + (lane & 3)];
                        a[mf][2] = As[rb * 33 + kb + (lane & 3) + 4];
                        a[mf][3] = As[(rb + 8) * 33 + kb + (lane & 3) + 4];
                    }
#pragma unroll
                    for (int nf = 0; nf < 3; nf++) {
                        int cb = wn + nf * 8 + (lane >> 2);
                        b[nf][0] = Ws[cb * WSP + kc + kb + (lane & 3)];
                        b[nf][1] = Ws[cb * WSP + kc + kb + (lane & 3) + 4];
                    }
#pragma unroll
                    for (int mf = 0; mf < 2; mf++)
#pragma unroll
                        for (int nf = 0; nf < 3; nf++)
                            mma8(acc[mf][nf], a[mf], b[nf]);
                }
                __syncthreads();
            }
        }
        // accumulators -> hg slice in SMEM
#pragma unroll
        for (int mf = 0; mf < 2; mf++)
#pragma unroll
            for (int nf = 0; nf < 3; nf++) {
                int row = wm + mf * 16 + (lane >> 2);
                int col = wn + nf * 8 + 2 * (lane & 3);
                hgS[row * 49 + col]           = acc[mf][nf][0];
                hgS[row * 49 + col + 1]       = acc[mf][nf][1];
                hgS[(row + 8) * 49 + col]     = acc[mf][nf][2];
                hgS[(row + 8) * 49 + col + 1] = acc[mf][nf][3];
            }
        __syncthreads();
        // gate epilogue: 64 batches x 16 cols = 1024 items / 128 threads
        {
            const int j = tid & 15;
#pragma unroll
            for (int it = 0; it < 8; it++) {
                int bb = (tid >> 4) + it * 8;
                size_t m = (size_t)bb * 512 + t;
                const float* xrow = xg + m * (size_t)(3 * H);
                float xr = xrow[c0 + j];
                float xz = xrow[H + c0 + j];
                float xn = xrow[2 * H + c0 + j];
                float hr = hgS[bb * 49 + j];
                float hz = hgS[bb * 49 + 16 + j];
                float hn = hgS[bb * 49 + 32 + j];
                float r = 1.f / (1.f + __expf(-(xr + hr)));
                float z = 1.f / (1.f + __expf(-(xz + hz)));
                float n = tanhf(xn + r * hn);
                float hnew = (1.f - z) * n + z * hl[bb * 16 + j];
                hl[bb * 16 + j] = hnew;
                __stcg(&g_h[bb * H + c0 + j], hnew);
                y[m * (size_t)H + c0 + j] = hnew;
            }
        }
        if (t < 511) {
            // grid barrier: release h writes, acquire others'
            __syncthreads();
            if (tid == 0) {
                unsigned prev;
                asm volatile("atom.release.gpu.add.u32 %0, [%1], 1;"
                             : "=r"(prev) : "l"(&g_arrive) : "memory");
                unsigned tgt = nCTA * (unsigned)(t + 1);
                if (prev + 1u == tgt) {
                    asm volatile("st.release.gpu.u32 [%0], %1;"
                                 :: "l"(&g_release), "r"((unsigned)(t + 1)) : "memory");
                } else {
                    unsigned v;
                    do {
                        asm volatile("ld.acquire.gpu.u32 %0, [%1];"
                                     : "=r"(v) : "l"(&g_release) : "memory");
                    } while (v < (unsigned)(t + 1));
                }
            }
            __syncthreads();
        }
    }
}

// ---------------- LayerNorm (eps=0) ----------------
template<int H>
__global__ void __launch_bounds__(128) ln_k(const float* __restrict__ yin,
                                            const float* __restrict__ gw,
                                            const float* __restrict__ bw,
                                            float* __restrict__ outp) {
    constexpr int PER = H / 128;
    __shared__ float red[8];
    const int row = blockIdx.x, tid = threadIdx.x;
    const float* p = yin + (size_t)row * H;
    float v[PER];
    float s = 0.f;
#pragma unroll
    for (int i = 0; i < PER; i++) { v[i] = p[tid + i * 128]; s += v[i]; }
#pragma unroll
    for (int o = 16; o > 0; o >>= 1) s += __shfl_xor_sync(0xffffffffu, s, o);
    if ((tid & 31) == 0) red[tid >> 5] = s;
    __syncthreads();
    float mean = (red[0] + red[1] + red[2] + red[3]) * (1.f / H);
    float s2 = 0.f;
#pragma unroll
    for (int i = 0; i < PER; i++) { float d = v[i] - mean; s2 += d * d; }
#pragma unroll
    for (int o = 16; o > 0; o >>= 1) s2 += __shfl_xor_sync(0xffffffffu, s2, o);
    if ((tid & 31) == 0) red[4 + (tid >> 5)] = s2;
    __syncthreads();
    float var = (red[4] + red[5] + red[6] + red[7]) * (1.f / H);
    float inv = rsqrtf(var);
#pragma unroll
    for (int i = 0; i < PER; i++) {
        int c = tid + i * 128;
        outp[(size_t)row * H + c] = (v[i] - mean) * inv * gw[c] + bw[c];
    }
}

__global__ void reset_bar() { g_arrive = 0u; g_release = 0u; }

// ---------------- driver ----------------
static inline size_t rec_smem(int H) {
    return sizeof(unsigned) * (48 * (H + 1) + 64 * 33) + sizeof(float) * (64 * 49 + 64 * 16);
}

extern "C" void kernel_launch(void* const* d_in, const int* in_sizes, int n_in,
                              void* d_out, int out_size) {
    (void)in_sizes; (void)n_in; (void)out_size;
    const float* x = (const float*)d_in[0];
    const float* Wih[6]; const float* Whh[6]; const float* gw[6]; const float* bw[6];
    for (int l = 0; l < 6; l++) {
        Wih[l] = (const float*)d_in[1 + 4 * l];
        Whh[l] = (const float*)d_in[2 + 4 * l];
        gw[l]  = (const float*)d_in[3 + 4 * l];
        bw[l]  = (const float*)d_in[4 + 4 * l];
    }
    float *xg, *actA, *actB;
    cudaGetSymbolAddress((void**)&xg, g_xg);
    cudaGetSymbolAddress((void**)&actA, g_actA);
    cudaGetSymbolAddress((void**)&actB, g_actB);

    static const int DIN[6] = {128, 256, 512, 1024, 512, 256};
    static const int HH[6]  = {256, 512, 1024, 512, 256, 128};

    const float* in = x;
    for (int l = 0; l < 6; l++) {
        const int K = DIN[l], H = HH[l], N = 3 * H;
        dim3 grid(N / 64, 256);
        switch (K) {
            case 128:  gemm_xg<128><<<grid, 256>>>(in, Wih[l], xg, N); break;
            case 256:  gemm_xg<256><<<grid, 256>>>(in, Wih[l], xg, N); break;
            case 512:  gemm_xg<512><<<grid, 256>>>(in, Wih[l], xg, N); break;
            case 1024: gemm_xg<1024><<<grid, 256>>>(in, Wih[l], xg, N); break;
        }
        reset_bar<<<1, 1>>>();
        const size_t sm = rec_smem(H);
        switch (H) {
            case 128:
                cudaFuncSetAttribute(gru_rec<128>, cudaFuncAttributeMaxDynamicSharedMemorySize, (int)sm);
                gru_rec<128><<<128 / 16, 128, sm>>>(Whh[l], xg, actB); break;
            case 256:
                cudaFuncSetAttribute(gru_rec<256>, cudaFuncAttributeMaxDynamicSharedMemorySize, (int)sm);
                gru_rec<256><<<256 / 16, 128, sm>>>(Whh[l], xg, actB); break;
            case 512:
                cudaFuncSetAttribute(gru_rec<512>, cudaFuncAttributeMaxDynamicSharedMemorySize, (int)sm);
                gru_rec<512><<<512 / 16, 128, sm>>>(Whh[l], xg, actB); break;
            case 1024:
                cudaFuncSetAttribute(gru_rec<1024>, cudaFuncAttributeMaxDynamicSharedMemorySize, (int)sm);
                gru_rec<1024><<<1024 / 16, 128, sm>>>(Whh[l], xg, actB); break;
        }
        float* lnout = (l == 5) ? (float*)d_out : actA;
        switch (H) {
            case 128:  ln_k<128><<<32768, 128>>>(actB, gw[l], bw[l], lnout); break;
            case 256:  ln_k<256><<<32768, 128>>>(actB, gw[l], bw[l], lnout); break;
            case 512:  ln_k<512><<<32768, 128>>>(actB, gw[l], bw[l], lnout); break;
            case 1024: ln_k<1024><<<32768, 128>>>(actB, gw[l], bw[l], lnout); break;
        }
        in = actA;
    }
}

// round 3
// speedup vs baseline: 2.0917x; 2.0879x over previous
#include <cuda_runtime.h>
#include <cstdint>

// ---------------- static scratch (no allocs allowed) ----------------
__device__ float g_xg[32768 * 3072];      // input-projection buffer (max 3H=3072)
__device__ float g_actA[32768 * 1024];    // layer activations ping
__device__ float g_actB[32768 * 1024];    // raw GRU outputs (pre-LN)
__device__ unsigned g_h[64 * 1024];       // current hidden state broadcast (tf32 bit patterns)
__device__ unsigned g_arrive;
__device__ unsigned g_release;

// ---------------- helpers ----------------
__device__ __forceinline__ unsigned f2tf(float x) {
    unsigned r; asm("cvt.rna.tf32.f32 %0, %1;" : "=r"(r) : "f"(x)); return r;
}

__device__ __forceinline__ void mma8(float* c, const unsigned* a, const unsigned* b) {
    asm volatile("mma.sync.aligned.m16n8k8.row.col.f32.tf32.tf32.f32 "
                 "{%0,%1,%2,%3}, {%4,%5,%6,%7}, {%8,%9}, {%0,%1,%2,%3};"
                 : "+f"(c[0]), "+f"(c[1]), "+f"(c[2]), "+f"(c[3])
                 : "r"(a[0]), "r"(a[1]), "r"(a[2]), "r"(a[3]),
                   "r"(b[0]), "r"(b[1]));
}

// ---------------- input-projection GEMM: C[m,n] = sum_k A[m,k]*B[n,k] ----------------
// A: [32768, K] row-major, B: [N, K] row-major, C: [32768, N]
// CTA tile 128x64, 8 warps (4M x 2N), warp tile 32x32 (2 m-frags x 4 n-frags)
template<int K>
__global__ void __launch_bounds__(256) gemm_xg(const float* __restrict__ A,
                                               const float* __restrict__ B,
                                               float* __restrict__ C, int N) {
    __shared__ unsigned As[128 * 36];
    __shared__ unsigned Bs[64 * 36];
    const int m0 = blockIdx.y * 128;
    const int n0 = blockIdx.x * 64;
    const int tid = threadIdx.x;
    const int lane = tid & 31, wid = tid >> 5;
    const int wm = (wid & 3) * 32, wn = (wid >> 2) * 32;

    float acc[2][4][4];
#pragma unroll
    for (int i = 0; i < 2; i++)
#pragma unroll
        for (int j = 0; j < 4; j++)
#pragma unroll
            for (int k = 0; k < 4; k++) acc[i][j][k] = 0.f;

    const int lr = tid >> 3;        // 0..31
    const int lc = (tid & 7) * 4;   // 0..28

    for (int kc = 0; kc < K; kc += 32) {
#pragma unroll
        for (int i = 0; i < 4; i++) {
            int r = lr + i * 32;
            float4 v = *reinterpret_cast<const float4*>(&A[(size_t)(m0 + r) * K + kc + lc]);
            As[r * 36 + lc + 0] = f2tf(v.x); As[r * 36 + lc + 1] = f2tf(v.y);
            As[r * 36 + lc + 2] = f2tf(v.z); As[r * 36 + lc + 3] = f2tf(v.w);
        }
#pragma unroll
        for (int i = 0; i < 2; i++) {
            int r = lr + i * 32;
            float4 v = *reinterpret_cast<const float4*>(&B[(size_t)(n0 + r) * K + kc + lc]);
            Bs[r * 36 + lc + 0] = f2tf(v.x); Bs[r * 36 + lc + 1] = f2tf(v.y);
            Bs[r * 36 + lc + 2] = f2tf(v.z); Bs[r * 36 + lc + 3] = f2tf(v.w);
        }
        __syncthreads();
#pragma unroll
        for (int k8 = 0; k8 < 4; k8++) {
            const int kb = k8 * 8;
            unsigned a[2][4], b[4][2];
#pragma unroll
            for (int mf = 0; mf < 2; mf++) {
                int rb = wm + mf * 16 + (lane >> 2);
                a[mf][0] = As[rb * 36 + kb + (lane & 3)];
                a[mf][1] = As[(rb + 8) * 36 + kb + (lane & 3)];
                a[mf][2] = As[rb * 36 + kb + (lane & 3) + 4];
                a[mf][3] = As[(rb + 8) * 36 + kb + (lane & 3) + 4];
            }
#pragma unroll
            for (int nf = 0; nf < 4; nf++) {
                int cb = wn + nf * 8 + (lane >> 2);
                b[nf][0] = Bs[cb * 36 + kb + (lane & 3)];
                b[nf][1] = Bs[cb * 36 + kb + (lane & 3) + 4];
            }
#pragma unroll
            for (int mf = 0; mf < 2; mf++)
#pragma unroll
                for (int nf = 0; nf < 4; nf++)
                    mma8(acc[mf][nf], a[mf], b[nf]);
        }
        __syncthreads();
    }
#pragma unroll
    for (int mf = 0; mf < 2; mf++)
#pragma unroll
        for (int nf = 0; nf < 4; nf++) {
            int row = m0 + wm + mf * 16 + (lane >> 2);
            int col = n0 + wn + nf * 8 + 2 * (lane & 3);
            C[(size_t)row * N + col]     = acc[mf][nf][0];
            C[(size_t)row * N + col + 1] = acc[mf][nf][1];
            C[(size_t)(row + 8) * N + col]     = acc[mf][nf][2];
            C[(size_t)(row + 8) * N + col + 1] = acc[mf][nf][3];
        }
}

// ---------------- persistent GRU recurrence (pipelined) ----------------
// grid = H/16 CTAs (all co-resident), block = 256 threads, 8 warps (4M x 2N).
// Each CTA owns 16 h-columns; its 48xH Whh slice lives in SMEM (tf32) for all 512 steps.
// g_h holds tf32 bit patterns (pre-converted at store), so A staging is a raw copy.
template<int H>
__global__ void __launch_bounds__(256) gru_rec(const float* __restrict__ Whh,
                                               const float* __restrict__ xg,
                                               float* __restrict__ y) {
    constexpr int WSP = H + 4;              // conflict-free pad (== 4 mod 32)
    constexpr int NCH = H / 32;
    extern __shared__ unsigned char smem_raw[];
    unsigned* Ws = reinterpret_cast<unsigned*>(smem_raw);   // [48][WSP] tf32 Whh slice
    unsigned* As = Ws + 48 * WSP;                           // 2 x [64][36] tf32 h chunk
    float* hgS = reinterpret_cast<float*>(As + 2 * 64 * 36);// [64][52] hg slice

    const int tid = threadIdx.x;
    const int lane = tid & 31, wid = tid >> 5;
    const int wm = (wid & 3) * 16;
    const int wn = (wid >> 2) * 24;
    const int c0 = blockIdx.x * 16;
    const unsigned nCTA = gridDim.x;
    const int q = lane >> 2, r4 = lane & 3;
    const int rb = wm + q;

    // one-time: Whh slice -> SMEM (tf32)
    {
        constexpr int nf4 = H / 4;
        for (int idx = tid; idx < 48 * nf4; idx += 256) {
            int rr = idx / nf4;
            int c4 = (idx % nf4) * 4;
            int gate = rr >> 4;
            int jj = rr & 15;
            int grow = gate * H + c0 + jj;
            float4 v = *reinterpret_cast<const float4*>(&Whh[(size_t)grow * H + c4]);
            Ws[rr * WSP + c4 + 0] = f2tf(v.x); Ws[rr * WSP + c4 + 1] = f2tf(v.y);
            Ws[rr * WSP + c4 + 2] = f2tf(v.z); Ws[rr * WSP + c4 + 3] = f2tf(v.w);
        }
    }
    __syncthreads();

    const int j = tid & 15;
    const int bbase = tid >> 4;             // 0..15
    float hl[4] = {0.f, 0.f, 0.f, 0.f};     // local h (own cols), register-resident

    // staging-copy index map: 512 float4 = 64 rows x 8 col-groups, 2 per thread
    const int i0r = tid >> 3,          i0c = (tid & 7) * 4;
    const int i1r = (tid + 256) >> 3,  i1c = (tid & 7) * 4;   // (tid+256)&7 == tid&7

    for (int t = 0; t < 512; t++) {
        // -------- xg prefetch (independent of h; hidden under GEMM) --------
        float pxr[4], pxz[4], pxn[4];
#pragma unroll
        for (int it = 0; it < 4; it++) {
            int bb = bbase + it * 16;
            const float* xrow = xg + ((size_t)bb * 512 + t) * (size_t)(3 * H);
            pxr[it] = __ldcs(xrow + c0 + j);
            pxz[it] = __ldcs(xrow + H + c0 + j);
            pxn[it] = __ldcs(xrow + 2 * H + c0 + j);
        }

        float acc[3][4];
#pragma unroll
        for (int nf = 0; nf < 3; nf++)
#pragma unroll
            for (int k = 0; k < 4; k++) acc[nf][k] = 0.f;

        if (t > 0) {
            uint4 pre0, pre1;
            // chunk 0: load + stage
            pre0 = __ldcg(reinterpret_cast<const uint4*>(&g_h[i0r * H + i0c]));
            pre1 = __ldcg(reinterpret_cast<const uint4*>(&g_h[i1r * H + i1c]));
            *reinterpret_cast<uint4*>(&As[i0r * 36 + i0c]) = pre0;
            *reinterpret_cast<uint4*>(&As[i1r * 36 + i1c]) = pre1;

            for (int ch = 0; ch < NCH; ch++) {
                __syncthreads();
                if (ch + 1 < NCH) {
                    const int kc = (ch + 1) * 32;
                    pre0 = __ldcg(reinterpret_cast<const uint4*>(&g_h[i0r * H + kc + i0c]));
                    pre1 = __ldcg(reinterpret_cast<const uint4*>(&g_h[i1r * H + kc + i1c]));
                }
                const unsigned* Ab = As + (ch & 1) * (64 * 36);
                const int kc = ch * 32;
#pragma unroll
                for (int k8 = 0; k8 < 4; k8++) {
                    const int kb = k8 * 8;
                    unsigned a[4], b[3][2];
                    a[0] = Ab[rb * 36 + kb + r4];
                    a[1] = Ab[(rb + 8) * 36 + kb + r4];
                    a[2] = Ab[rb * 36 + kb + r4 + 4];
                    a[3] = Ab[(rb + 8) * 36 + kb + r4 + 4];
#pragma unroll
                    for (int nf = 0; nf < 3; nf++) {
                        int cb = wn + nf * 8 + q;
                        b[nf][0] = Ws[cb * WSP + kc + kb + r4];
                        b[nf][1] = Ws[cb * WSP + kc + kb + r4 + 4];
                    }
#pragma unroll
                    for (int nf = 0; nf < 3; nf++)
                        mma8(acc[nf], a, b[nf]);
                }
                if (ch + 1 < NCH) {
                    unsigned* Bb = As + ((ch + 1) & 1) * (64 * 36);
                    *reinterpret_cast<uint4*>(&Bb[i0r * 36 + i0c]) = pre0;
                    *reinterpret_cast<uint4*>(&Bb[i1r * 36 + i1c]) = pre1;
                }
            }
        }
        // -------- accumulators -> hg slice in SMEM --------
#pragma unroll
        for (int nf = 0; nf < 3; nf++) {
            int row = wm + q;
            int col = wn + nf * 8 + 2 * r4;
            hgS[row * 52 + col]           = acc[nf][0];
            hgS[row * 52 + col + 1]       = acc[nf][1];
            hgS[(row + 8) * 52 + col]     = acc[nf][2];
            hgS[(row + 8) * 52 + col + 1] = acc[nf][3];
        }
        __syncthreads();
        // -------- gate epilogue: 64 batches x 16 cols / 256 threads --------
#pragma unroll
        for (int it = 0; it < 4; it++) {
            int bb = bbase + it * 16;
            float hr = hgS[bb * 52 + j];
            float hz = hgS[bb * 52 + 16 + j];
            float hn = hgS[bb * 52 + 32 + j];
            float r = 1.f / (1.f + __expf(-(pxr[it] + hr)));
            float z = 1.f / (1.f + __expf(-(pxz[it] + hz)));
            float n = tanhf(pxn[it] + r * hn);
            float hnew = (1.f - z) * n + z * hl[it];
            hl[it] = hnew;
            __stcg(&g_h[bb * H + c0 + j], f2tf(hnew));
            y[((size_t)bb * 512 + t) * (size_t)H + c0 + j] = hnew;
        }
        if (t < 511) {
            __syncthreads();
            if (tid == 0) {
                unsigned prev;
                asm volatile("atom.release.gpu.add.u32 %0, [%1], 1;"
                             : "=r"(prev) : "l"(&g_arrive) : "memory");
                unsigned tgt = nCTA * (unsigned)(t + 1);
                if (prev + 1u == tgt) {
                    asm volatile("st.release.gpu.u32 [%0], %1;"
                                 :: "l"(&g_release), "r"((unsigned)(t + 1)) : "memory");
                } else {
                    unsigned v;
                    do {
                        asm volatile("ld.acquire.gpu.u32 %0, [%1];"
                                     : "=r"(v) : "l"(&g_release) : "memory");
                    } while (v < (unsigned)(t + 1));
                }
            }
            __syncthreads();
        }
    }
}

// ---------------- LayerNorm (eps=0) ----------------
template<int H>
__global__ void __launch_bounds__(128) ln_k(const float* __restrict__ yin,
                                            const float* __restrict__ gw,
                                            const float* __restrict__ bw,
                                            float* __restrict__ outp) {
    constexpr int PER = H / 128;
    __shared__ float red[8];
    const int row = blockIdx.x, tid = threadIdx.x;
    const float* p = yin + (size_t)row * H;
    float v[PER];
    float s = 0.f;
#pragma unroll
    for (int i = 0; i < PER; i++) { v[i] = p[tid + i * 128]; s += v[i]; }
#pragma unroll
    for (int o = 16; o > 0; o >>= 1) s += __shfl_xor_sync(0xffffffffu, s, o);
    if ((tid & 31) == 0) red[tid >> 5] = s;
    __syncthreads();
    float mean = (red[0] + red[1] + red[2] + red[3]) * (1.f / H);
    float s2 = 0.f;
#pragma unroll
    for (int i = 0; i < PER; i++) { float d = v[i] - mean; s2 += d * d; }
#pragma unroll
    for (int o = 16; o > 0; o >>= 1) s2 += __shfl_xor_sync(0xffffffffu, s2, o);
    if ((tid & 31) == 0) red[4 + (tid >> 5)] = s2;
    __syncthreads();
    float var = (red[4] + red[5] + red[6] + red[7]) * (1.f / H);
    float inv = rsqrtf(var);
#pragma unroll
    for (int i = 0; i < PER; i++) {
        int c = tid + i * 128;
        outp[(size_t)row * H + c] = (v[i] - mean) * inv * gw[c] + bw[c];
    }
}

__global__ void reset_bar() { g_arrive = 0u; g_release = 0u; }

// ---------------- driver ----------------
static inline size_t rec_smem(int H) {
    return sizeof(unsigned) * (48 * (H + 4) + 2 * 64 * 36) + sizeof(float) * (64 * 52);
}

extern "C" void kernel_launch(void* const* d_in, const int* in_sizes, int n_in,
                              void* d_out, int out_size) {
    (void)in_sizes; (void)n_in; (void)out_size;
    const float* x = (const float*)d_in[0];
    const float* Wih[6]; const float* Whh[6]; const float* gw[6]; const float* bw[6];
    for (int l = 0; l < 6; l++) {
        Wih[l] = (const float*)d_in[1 + 4 * l];
        Whh[l] = (const float*)d_in[2 + 4 * l];
        gw[l]  = (const float*)d_in[3 + 4 * l];
        bw[l]  = (const float*)d_in[4 + 4 * l];
    }
    float *xg, *actA, *actB;
    cudaGetSymbolAddress((void**)&xg, g_xg);
    cudaGetSymbolAddress((void**)&actA, g_actA);
    cudaGetSymbolAddress((void**)&actB, g_actB);

    static const int DIN[6] = {128, 256, 512, 1024, 512, 256};
    static const int HH[6]  = {256, 512, 1024, 512, 256, 128};

    const float* in = x;
    for (int l = 0; l < 6; l++) {
        const int K = DIN[l], H = HH[l], N = 3 * H;
        dim3 grid(N / 64, 256);
        switch (K) {
            case 128:  gemm_xg<128><<<grid, 256>>>(in, Wih[l], xg, N); break;
            case 256:  gemm_xg<256><<<grid, 256>>>(in, Wih[l], xg, N); break;
            case 512:  gemm_xg<512><<<grid, 256>>>(in, Wih[l], xg, N); break;
            case 1024: gemm_xg<1024><<<grid, 256>>>(in, Wih[l], xg, N); break;
        }
        reset_bar<<<1, 1>>>();
        const size_t sm = rec_smem(H);
        switch (H) {
            case 128:
                cudaFuncSetAttribute(gru_rec<128>, cudaFuncAttributeMaxDynamicSharedMemorySize, (int)sm);
                gru_rec<128><<<128 / 16, 256, sm>>>(Whh[l], xg, actB); break;
            case 256:
                cudaFuncSetAttribute(gru_rec<256>, cudaFuncAttributeMaxDynamicSharedMemorySize, (int)sm);
                gru_rec<256><<<256 / 16, 256, sm>>>(Whh[l], xg, actB); break;
            case 512:
                cudaFuncSetAttribute(gru_rec<512>, cudaFuncAttributeMaxDynamicSharedMemorySize, (int)sm);
                gru_rec<512><<<512 / 16, 256, sm>>>(Whh[l], xg, actB); break;
            case 1024:
                cudaFuncSetAttribute(gru_rec<1024>, cudaFuncAttributeMaxDynamicSharedMemorySize, (int)sm);
                gru_rec<1024><<<1024 / 16, 256, sm>>>(Whh[l], xg, actB); break;
        }
        float* lnout = (l == 5) ? (float*)d_out : actA;
        switch (H) {
            case 128:  ln_k<128><<<32768, 128>>>(actB, gw[l], bw[l], lnout); break;
            case 256:  ln_k<256><<<32768, 128>>>(actB, gw[l], bw[l], lnout); break;
            case 512:  ln_k<512><<<32768, 128>>>(actB, gw[l], bw[l], lnout); break;
            case 1024: ln_k<1024><<<32768, 128>>>(actB, gw[l], bw[l], lnout); break;
        }
        in = actA;
    }
}